// round 1
// baseline (speedup 1.0000x reference)
#include <cuda_runtime.h>
#include <math.h>

// ---------------- problem constants ----------------
#define BB   8
#define SS   2048
#define EE   1024
#define HH   16
#define OO   8      // ORDER
#define CCH_ 8      // CHUNK (per-head inner)
#define DFF  4096
#define NTOK (BB*SS)                // 16384
#define SCALE_UP 0.16f
#define OUT_SCALE 128.0f
#define LN_EPS 1e-5f

// scan chunking
#define NCHUNK 64                   // chunks along S
#define CLEN   (SS/NCHUNK)          // 32 steps per chunk

// ---------------- scratch (static device globals; no allocation) ----------------
__device__ float g_M [(size_t)BB*HH*SS*64];     // [b*H+h][s][8][8]   64 MB
__device__ float g_cp[(size_t)BB*HH*NCHUNK*64]; // chunk products
__device__ float g_ex[(size_t)BB*HH*NCHUNK*64]; // exclusive chunk prefixes
__device__ float g_y [(size_t)NTOK*EE];         // MRU branch output   64 MB
__device__ float g_x1[(size_t)NTOK*EE];         // x after first residual
__device__ float g_h2[(size_t)NTOK*EE];         // LN(x1)
__device__ float g_g [(size_t)NTOK*DFF];        // gelu(h2@ffn_up^T)  256 MB

// ---------------- helpers ----------------
__device__ __forceinline__ void blockReduce2(float& a, float& b) {
    #pragma unroll
    for (int o = 16; o; o >>= 1) {
        a += __shfl_down_sync(0xffffffffu, a, o);
        b += __shfl_down_sync(0xffffffffu, b, o);
    }
    __shared__ float ra[8], rb[8];
    int w = threadIdx.x >> 5, l = threadIdx.x & 31;
    if (l == 0) { ra[w] = a; rb[w] = b; }
    __syncthreads();
    float sa = 0.f, sb = 0.f;
    #pragma unroll
    for (int i = 0; i < 8; i++) { sa += ra[i]; sb += rb[i]; }
    a = sa; b = sb;
}

__device__ __forceinline__ float gelu_exact(float v) {
    return 0.5f * v * (1.0f + erff(v * 0.70710678118654752f));
}

// ---------------- kernel A: LayerNorm(x, mru_norm_w) fused with M construction ----------------
// one block per token, 256 threads
__global__ __launch_bounds__(256) void k_ln_M(
    const float* __restrict__ x, const float* __restrict__ w,
    const float* __restrict__ up)
{
    int tok = blockIdx.x;             // b*S + s
    int b = tok / SS, s = tok % SS;
    __shared__ float xs[EE];
    __shared__ float ups[EE];         // up: [H][CHUNK][ORDER] = 1024 floats

    const float* xr = x + (size_t)tok * EE;
    float lsum = 0.f, lsq = 0.f;
    for (int i = threadIdx.x; i < EE; i += 256) {
        float v = xr[i];
        xs[i] = v; ups[i] = up[i];
        lsum += v; lsq += v * v;
    }
    blockReduce2(lsum, lsq);          // contains __syncthreads -> xs/ups visible
    float mu = lsum * (1.0f / EE);
    float var = lsq * (1.0f / EE) - mu * mu;
    float rstd = rsqrtf(var + LN_EPS);

    for (int i = threadIdx.x; i < EE; i += 256)
        xs[i] = (xs[i] - mu) * rstd * w[i];
    __syncthreads();

    // M[h][o][p] = 0.16 * sum_c h[h*64+o*8+c] * up[h*64+c*8+p] + (o==p)
    for (int e = threadIdx.x; e < 1024; e += 256) {
        int h = e >> 6, o = (e >> 3) & 7, p = e & 7;
        const float* hr = xs + h * 64 + o * 8;
        const float* ur = ups + h * 64 + p;
        float acc = 0.f;
        #pragma unroll
        for (int c = 0; c < 8; c++) acc += hr[c] * ur[c * 8];
        acc = acc * SCALE_UP + ((o == p) ? 1.0f : 0.0f);
        g_M[(((size_t)(b * HH + h)) * SS + s) * 64 + (e & 63)] = acc;
    }
}

// ---------------- kernel B: per-chunk matrix products ----------------
// grid = B*H*NCHUNK, 64 threads; P = M[t0] @ M[t0+1] @ ... (left-to-right)
__global__ __launch_bounds__(64) void k_chunkprod()
{
    int blk = blockIdx.x;
    int bh = blk / NCHUNK, c = blk % NCHUNK;
    int t = threadIdx.x, i = t >> 3, j = t & 7;
    __shared__ float P[64], Mm[64];
    P[t] = (i == j) ? 1.0f : 0.0f;
    const float* Mb = g_M + (((size_t)bh * SS + (size_t)c * CLEN)) * 64;
    for (int st = 0; st < CLEN; st++) {
        Mm[t] = Mb[(size_t)st * 64 + t];
        __syncthreads();
        float acc = 0.f;
        #pragma unroll
        for (int k = 0; k < 8; k++) acc += P[i * 8 + k] * Mm[k * 8 + j];
        __syncthreads();
        P[t] = acc;
    }
    __syncthreads();
    g_cp[((size_t)blk) * 64 + t] = P[t];
}

// ---------------- kernel C: exclusive scan over chunk products (per bh) ----------------
__global__ __launch_bounds__(64) void k_scanchunks()
{
    int bh = blockIdx.x;
    int t = threadIdx.x, i = t >> 3, j = t & 7;
    __shared__ float P[64], Mm[64];
    P[t] = (i == j) ? 1.0f : 0.0f;
    for (int c = 0; c < NCHUNK; c++) {
        Mm[t] = g_cp[((size_t)(bh * NCHUNK + c)) * 64 + t];
        __syncthreads();
        g_ex[((size_t)(bh * NCHUNK + c)) * 64 + t] = P[t];   // exclusive prefix
        float acc = 0.f;
        #pragma unroll
        for (int k = 0; k < 8; k++) acc += P[i * 8 + k] * Mm[k * 8 + j];
        __syncthreads();
        P[t] = acc;
    }
}

// ---------------- kernel D: replay chunks -> states, y, states[B-1] output ----------------
__global__ __launch_bounds__(64) void k_states_y(
    const float* __restrict__ down, float* __restrict__ out_states)
{
    int blk = blockIdx.x;
    int bh = blk / NCHUNK, c = blk % NCHUNK;
    int b = bh / HH, h = bh % HH;
    int t = threadIdx.x, i = t >> 3, j = t & 7;
    __shared__ float P[64], Mm[64], dn[64];
    P[t] = g_ex[((size_t)blk) * 64 + t];
    dn[t] = down[h * 64 + t];                 // down: [H][ORDER][CHUNK]
    const float* Mb = g_M + (((size_t)bh * SS + (size_t)c * CLEN)) * 64;
    bool last = (b == BB - 1);
    for (int st = 0; st < CLEN; st++) {
        Mm[t] = Mb[(size_t)st * 64 + t];
        __syncthreads();
        float acc = 0.f;
        #pragma unroll
        for (int k = 0; k < 8; k++) acc += P[i * 8 + k] * Mm[k * 8 + j];
        __syncthreads();
        P[t] = acc;
        __syncthreads();                      // all of P needed for y
        int s = c * CLEN + st;
        float yv = 0.f;
        #pragma unroll
        for (int p = 0; p < 8; p++) yv += P[i * 8 + p] * dn[p * 8 + j];
        // y layout: [B,S,H,O,CH] -> E index h*64 + o*8 + c2 = h*64 + t
        g_y[(((size_t)(b * SS + s)) << 10) + h * 64 + t] = yv * OUT_SCALE;
        if (last)
            out_states[(((size_t)(s * HH + h)) << 6) + t] = P[t];
    }
}

// ---------------- standalone LayerNorm (FFN pre-norm) ----------------
__global__ __launch_bounds__(256) void k_ln(
    const float* __restrict__ x, const float* __restrict__ w, float* __restrict__ out)
{
    int tok = blockIdx.x;
    const float* xr = x + (size_t)tok * EE;
    __shared__ float xs[EE];
    float lsum = 0.f, lsq = 0.f;
    for (int i = threadIdx.x; i < EE; i += 256) {
        float v = xr[i]; xs[i] = v; lsum += v; lsq += v * v;
    }
    blockReduce2(lsum, lsq);
    float mu = lsum * (1.0f / EE);
    float var = lsq * (1.0f / EE) - mu * mu;
    float rstd = rsqrtf(var + LN_EPS);
    for (int i = threadIdx.x; i < EE; i += 256)
        out[(size_t)tok * EE + i] = (xs[i] - mu) * rstd * w[i];
}

// ---------------- NT SGEMM: C[m,n] = epi( sum_k A[m,k]*B[n,k] (+Res) ) ----------------
// EPI: 0 plain, 1 residual add, 2 exact gelu
#define BM 128
#define BN 64
#define BK 16

template <int EPI>
__global__ __launch_bounds__(256) void sgemm_nt(
    const float* __restrict__ A, const float* __restrict__ Bm,
    const float* __restrict__ Res, float* __restrict__ D,
    int M, int N, int K)
{
    __shared__ float As[BK][BM];
    __shared__ float Bs[BK][BN];
    int tid = threadIdx.x;
    int m0 = blockIdx.y * BM;
    int n0 = blockIdx.x * BN;
    int tr = tid >> 4, tc = tid & 15;   // 16x16 thread grid, 8x4 per thread

    float acc[8][4];
    #pragma unroll
    for (int r = 0; r < 8; r++)
        #pragma unroll
        for (int c = 0; c < 4; c++) acc[r][c] = 0.f;

    const float* Aptr = A + (size_t)m0 * K;
    const float* Bptr = Bm + (size_t)n0 * K;

    for (int k0 = 0; k0 < K; k0 += BK) {
        // load A tile: 128x16 = 512 float4, 2 per thread
        #pragma unroll
        for (int rr = 0; rr < 2; rr++) {
            int idx = tid + rr * 256;
            int row = idx >> 2, kq = idx & 3;
            float4 v = *reinterpret_cast<const float4*>(Aptr + (size_t)row * K + k0 + kq * 4);
            As[kq * 4 + 0][row] = v.x; As[kq * 4 + 1][row] = v.y;
            As[kq * 4 + 2][row] = v.z; As[kq * 4 + 3][row] = v.w;
        }
        // load B tile: 64x16 = 256 float4, 1 per thread
        {
            int row = tid >> 2, kq = tid & 3;
            float4 v = *reinterpret_cast<const float4*>(Bptr + (size_t)row * K + k0 + kq * 4);
            Bs[kq * 4 + 0][row] = v.x; Bs[kq * 4 + 1][row] = v.y;
            Bs[kq * 4 + 2][row] = v.z; Bs[kq * 4 + 3][row] = v.w;
        }
        __syncthreads();
        #pragma unroll
        for (int kk = 0; kk < BK; kk++) {
            float4 a0 = *reinterpret_cast<const float4*>(&As[kk][tr * 8]);
            float4 a1 = *reinterpret_cast<const float4*>(&As[kk][tr * 8 + 4]);
            float4 b0 = *reinterpret_cast<const float4*>(&Bs[kk][tc * 4]);
            float ar[8] = {a0.x, a0.y, a0.z, a0.w, a1.x, a1.y, a1.z, a1.w};
            float br[4] = {b0.x, b0.y, b0.z, b0.w};
            #pragma unroll
            for (int r = 0; r < 8; r++)
                #pragma unroll
                for (int c = 0; c < 4; c++)
                    acc[r][c] += ar[r] * br[c];
        }
        __syncthreads();
    }

    #pragma unroll
    for (int r = 0; r < 8; r++) {
        int m = m0 + tr * 8 + r;
        int n = n0 + tc * 4;
        float4 v = make_float4(acc[r][0], acc[r][1], acc[r][2], acc[r][3]);
        if (EPI == 1) {
            float4 rv = *reinterpret_cast<const float4*>(Res + (size_t)m * N + n);
            v.x += rv.x; v.y += rv.y; v.z += rv.z; v.w += rv.w;
        } else if (EPI == 2) {
            v.x = gelu_exact(v.x); v.y = gelu_exact(v.y);
            v.z = gelu_exact(v.z); v.w = gelu_exact(v.w);
        }
        *reinterpret_cast<float4*>(D + (size_t)m * N + n) = v;
    }
}

// ---------------- launch ----------------
extern "C" void kernel_launch(void* const* d_in, const int* in_sizes, int n_in,
                              void* d_out, int out_size)
{
    (void)in_sizes; (void)n_in; (void)out_size;
    const float* x        = (const float*)d_in[0];
    const float* up       = (const float*)d_in[1];
    const float* down     = (const float*)d_in[2];
    const float* w_out    = (const float*)d_in[3];
    const float* mru_w    = (const float*)d_in[4];
    const float* ffn_w    = (const float*)d_in[5];
    const float* ffn_up   = (const float*)d_in[6];
    const float* ffn_down = (const float*)d_in[7];
    float* out = (float*)d_out;
    float* out_states = out + (size_t)NTOK * EE;   // second output: states[B-1] [S,H,8,8]

    float *p_y, *p_x1, *p_h2, *p_g;
    cudaGetSymbolAddress((void**)&p_y,  g_y);
    cudaGetSymbolAddress((void**)&p_x1, g_x1);
    cudaGetSymbolAddress((void**)&p_h2, g_h2);
    cudaGetSymbolAddress((void**)&p_g,  g_g);

    // MRU branch
    k_ln_M<<<NTOK, 256>>>(x, mru_w, up);
    k_chunkprod<<<BB * HH * NCHUNK, 64>>>();
    k_scanchunks<<<BB * HH, 64>>>();
    k_states_y<<<BB * HH * NCHUNK, 64>>>(down, out_states);

    // x1 = x + y @ w_out^T
    {
        dim3 grid(EE / BN, NTOK / BM);
        sgemm_nt<1><<<grid, 256>>>(p_y, w_out, x, p_x1, NTOK, EE, EE);
    }
    // h2 = LN(x1)
    k_ln<<<NTOK, 256>>>(p_x1, ffn_w, p_h2);
    // g = gelu(h2 @ ffn_up^T)
    {
        dim3 grid(DFF / BN, NTOK / BM);
        sgemm_nt<2><<<grid, 256>>>(p_h2, ffn_up, nullptr, p_g, NTOK, DFF, EE);
    }
    // out = x1 + g @ ffn_down^T
    {
        dim3 grid(EE / BN, NTOK / BM);
        sgemm_nt<1><<<grid, 256>>>(p_g, ffn_down, p_x1, out, NTOK, EE, DFF);
    }
}

// round 2
// speedup vs baseline: 2.9012x; 2.9012x over previous
#include <cuda_runtime.h>
#include <math.h>
#include <stdint.h>

// ---------------- problem constants ----------------
#define BB   8
#define SS   2048
#define EE   1024
#define HH   16
#define DFF  4096
#define NTOK (BB*SS)                // 16384
#define SCALE_UP 0.16f
#define OUT_SCALE 128.0f
#define LN_EPS 1e-5f

// scan chunking
#define NCHUNK 64
#define CLEN   (SS/NCHUNK)          // 32

// ---------------- scratch ----------------
__device__ float g_M [(size_t)BB*HH*SS*64];
__device__ float g_cp[(size_t)BB*HH*NCHUNK*64];
__device__ float g_ex[(size_t)BB*HH*NCHUNK*64];
__device__ float g_y [(size_t)NTOK*EE];
__device__ float g_x1[(size_t)NTOK*EE];
__device__ float g_h2[(size_t)NTOK*EE];
__device__ float g_g [(size_t)NTOK*DFF];

// ---------------- helpers ----------------
__device__ __forceinline__ void blockReduce2(float& a, float& b) {
    #pragma unroll
    for (int o = 16; o; o >>= 1) {
        a += __shfl_down_sync(0xffffffffu, a, o);
        b += __shfl_down_sync(0xffffffffu, b, o);
    }
    __shared__ float ra[8], rb[8];
    int w = threadIdx.x >> 5, l = threadIdx.x & 31;
    if (l == 0) { ra[w] = a; rb[w] = b; }
    __syncthreads();
    float sa = 0.f, sb = 0.f;
    #pragma unroll
    for (int i = 0; i < 8; i++) { sa += ra[i]; sb += rb[i]; }
    a = sa; b = sb;
}

__device__ __forceinline__ float gelu_exact(float v) {
    return 0.5f * v * (1.0f + erff(v * 0.70710678118654752f));
}

__device__ __forceinline__ float tf32r(float f) {
    uint32_t o;
    asm("cvt.rna.tf32.f32 %0, %1;" : "=r"(o) : "f"(f));
    return __uint_as_float(o);
}

// ---------------- kernel A: LN + M construction ----------------
__global__ __launch_bounds__(256) void k_ln_M(
    const float* __restrict__ x, const float* __restrict__ w,
    const float* __restrict__ up)
{
    int tok = blockIdx.x;
    int b = tok / SS, s = tok % SS;
    __shared__ float xs[EE];
    __shared__ float ups[EE];

    const float* xr = x + (size_t)tok * EE;
    float lsum = 0.f, lsq = 0.f;
    for (int i = threadIdx.x; i < EE; i += 256) {
        float v = xr[i];
        xs[i] = v; ups[i] = up[i];
        lsum += v; lsq += v * v;
    }
    blockReduce2(lsum, lsq);
    float mu = lsum * (1.0f / EE);
    float var = lsq * (1.0f / EE) - mu * mu;
    float rstd = rsqrtf(var + LN_EPS);

    for (int i = threadIdx.x; i < EE; i += 256)
        xs[i] = (xs[i] - mu) * rstd * w[i];
    __syncthreads();

    for (int e = threadIdx.x; e < 1024; e += 256) {
        int h = e >> 6, o = (e >> 3) & 7, p = e & 7;
        const float* hr = xs + h * 64 + o * 8;
        const float* ur = ups + h * 64 + p;
        float acc = 0.f;
        #pragma unroll
        for (int c = 0; c < 8; c++) acc += hr[c] * ur[c * 8];
        acc = acc * SCALE_UP + ((o == p) ? 1.0f : 0.0f);
        g_M[(((size_t)(b * HH + h)) * SS + s) * 64 + (e & 63)] = acc;
    }
}

// ---------------- kernel B: per-chunk matrix products ----------------
__global__ __launch_bounds__(64) void k_chunkprod()
{
    int blk = blockIdx.x;
    int bh = blk / NCHUNK, c = blk % NCHUNK;
    int t = threadIdx.x, i = t >> 3, j = t & 7;
    __shared__ float P[64], Mm[64];
    P[t] = (i == j) ? 1.0f : 0.0f;
    const float* Mb = g_M + (((size_t)bh * SS + (size_t)c * CLEN)) * 64;
    for (int st = 0; st < CLEN; st++) {
        Mm[t] = Mb[(size_t)st * 64 + t];
        __syncthreads();
        float acc = 0.f;
        #pragma unroll
        for (int k = 0; k < 8; k++) acc += P[i * 8 + k] * Mm[k * 8 + j];
        __syncthreads();
        P[t] = acc;
    }
    __syncthreads();
    g_cp[((size_t)blk) * 64 + t] = P[t];
}

// ---------------- kernel C: exclusive scan over chunk products ----------------
__global__ __launch_bounds__(64) void k_scanchunks()
{
    int bh = blockIdx.x;
    int t = threadIdx.x, i = t >> 3, j = t & 7;
    __shared__ float P[64], Mm[64];
    P[t] = (i == j) ? 1.0f : 0.0f;
    for (int c = 0; c < NCHUNK; c++) {
        Mm[t] = g_cp[((size_t)(bh * NCHUNK + c)) * 64 + t];
        __syncthreads();
        g_ex[((size_t)(bh * NCHUNK + c)) * 64 + t] = P[t];
        float acc = 0.f;
        #pragma unroll
        for (int k = 0; k < 8; k++) acc += P[i * 8 + k] * Mm[k * 8 + j];
        __syncthreads();
        P[t] = acc;
    }
}

// ---------------- kernel D: replay -> states, y, states[B-1] ----------------
__global__ __launch_bounds__(64) void k_states_y(
    const float* __restrict__ down, float* __restrict__ out_states)
{
    int blk = blockIdx.x;
    int bh = blk / NCHUNK, c = blk % NCHUNK;
    int b = bh / HH, h = bh % HH;
    int t = threadIdx.x, i = t >> 3, j = t & 7;
    __shared__ float P[64], Mm[64], dn[64];
    P[t] = g_ex[((size_t)blk) * 64 + t];
    dn[t] = down[h * 64 + t];
    const float* Mb = g_M + (((size_t)bh * SS + (size_t)c * CLEN)) * 64;
    bool last = (b == BB - 1);
    for (int st = 0; st < CLEN; st++) {
        Mm[t] = Mb[(size_t)st * 64 + t];
        __syncthreads();
        float acc = 0.f;
        #pragma unroll
        for (int k = 0; k < 8; k++) acc += P[i * 8 + k] * Mm[k * 8 + j];
        __syncthreads();
        P[t] = acc;
        __syncthreads();
        int s = c * CLEN + st;
        float yv = 0.f;
        #pragma unroll
        for (int p = 0; p < 8; p++) yv += P[i * 8 + p] * dn[p * 8 + j];
        g_y[(((size_t)(b * SS + s)) << 10) + h * 64 + t] = yv * OUT_SCALE;
        if (last)
            out_states[(((size_t)(s * HH + h)) << 6) + t] = P[t];
    }
}

// ---------------- standalone LayerNorm ----------------
__global__ __launch_bounds__(256) void k_ln(
    const float* __restrict__ x, const float* __restrict__ w, float* __restrict__ out)
{
    int tok = blockIdx.x;
    const float* xr = x + (size_t)tok * EE;
    __shared__ float xs[EE];
    float lsum = 0.f, lsq = 0.f;
    for (int i = threadIdx.x; i < EE; i += 256) {
        float v = xr[i]; xs[i] = v; lsum += v; lsq += v * v;
    }
    blockReduce2(lsum, lsq);
    float mu = lsum * (1.0f / EE);
    float var = lsq * (1.0f / EE) - mu * mu;
    float rstd = rsqrtf(var + LN_EPS);
    for (int i = threadIdx.x; i < EE; i += 256)
        out[(size_t)tok * EE + i] = (xs[i] - mu) * rstd * w[i];
}

// ---------------- TF32 tensor-core NT GEMM ----------------
// C[m,n] = epi( sum_k A[m,k]*B[n,k] (+Res) ),  BM=BN=128, BK=32, 256 thr (8 warps 2x4)
// Warp tile 64x32 = 4(m) x 4(n) m16n8k8 mma tiles.
#define GSTRIDE 36   // smem row stride in floats (pad 4) -> conflict-free frag reads

__device__ __forceinline__ void mma_tf32(
    float c[4], uint32_t a0, uint32_t a1, uint32_t a2, uint32_t a3,
    uint32_t b0, uint32_t b1)
{
    asm volatile(
        "mma.sync.aligned.m16n8k8.row.col.f32.tf32.tf32.f32 "
        "{%0,%1,%2,%3},{%4,%5,%6,%7},{%8,%9},{%0,%1,%2,%3};\n"
        : "+f"(c[0]), "+f"(c[1]), "+f"(c[2]), "+f"(c[3])
        : "r"(a0), "r"(a1), "r"(a2), "r"(a3), "r"(b0), "r"(b1));
}

template <int EPI>   // 0 plain, 1 residual, 2 gelu
__global__ __launch_bounds__(256) void tf32gemm_nt(
    const float* __restrict__ A, const float* __restrict__ Bm,
    const float* __restrict__ Res, float* __restrict__ D,
    int M, int N, int K)
{
    __shared__ float As[128 * GSTRIDE];
    __shared__ float Bs[128 * GSTRIDE];

    int tid = threadIdx.x;
    int lane = tid & 31, warp = tid >> 5;
    int wm = (warp >> 2) * 64;   // warp m offset in tile
    int wn = (warp & 3) * 32;    // warp n offset in tile
    int m0 = blockIdx.y * 128;
    int n0 = blockIdx.x * 128;

    int lrow = tid >> 3;         // 0..31
    int lc4  = (tid & 7) * 4;    // 0,4,...,28

    const float* Ag = A + (size_t)m0 * K + lc4;
    const float* Bg = Bm + (size_t)n0 * K + lc4;

    float4 ra[4], rb[4];
    #pragma unroll
    for (int i = 0; i < 4; i++) {
        ra[i] = *reinterpret_cast<const float4*>(Ag + (size_t)(lrow + 32 * i) * K);
        rb[i] = *reinterpret_cast<const float4*>(Bg + (size_t)(lrow + 32 * i) * K);
    }

    float acc[4][4][4];
    #pragma unroll
    for (int mi = 0; mi < 4; mi++)
        #pragma unroll
        for (int ni = 0; ni < 4; ni++)
            #pragma unroll
            for (int r = 0; r < 4; r++) acc[mi][ni][r] = 0.f;

    int ktiles = K >> 5;
    for (int kt = 0; kt < ktiles; kt++) {
        // store (tf32-rounded) tiles to smem
        #pragma unroll
        for (int i = 0; i < 4; i++) {
            float* pa = As + (lrow + 32 * i) * GSTRIDE + lc4;
            float* pb = Bs + (lrow + 32 * i) * GSTRIDE + lc4;
            pa[0] = tf32r(ra[i].x); pa[1] = tf32r(ra[i].y);
            pa[2] = tf32r(ra[i].z); pa[3] = tf32r(ra[i].w);
            pb[0] = tf32r(rb[i].x); pb[1] = tf32r(rb[i].y);
            pb[2] = tf32r(rb[i].z); pb[3] = tf32r(rb[i].w);
        }
        __syncthreads();

        if (kt + 1 < ktiles) {
            #pragma unroll
            for (int i = 0; i < 4; i++) {
                ra[i] = *reinterpret_cast<const float4*>(Ag + (size_t)(lrow + 32 * i) * K + (kt + 1) * 32);
                rb[i] = *reinterpret_cast<const float4*>(Bg + (size_t)(lrow + 32 * i) * K + (kt + 1) * 32);
            }
        }

        #pragma unroll
        for (int kk = 0; kk < 4; kk++) {
            int kb = kk * 8 + (lane & 3);
            uint32_t af[4][4], bf[4][2];
            #pragma unroll
            for (int mi = 0; mi < 4; mi++) {
                int r = wm + mi * 16 + (lane >> 2);
                af[mi][0] = __float_as_uint(As[r * GSTRIDE + kb]);
                af[mi][1] = __float_as_uint(As[(r + 8) * GSTRIDE + kb]);
                af[mi][2] = __float_as_uint(As[r * GSTRIDE + kb + 4]);
                af[mi][3] = __float_as_uint(As[(r + 8) * GSTRIDE + kb + 4]);
            }
            #pragma unroll
            for (int ni = 0; ni < 4; ni++) {
                int r = wn + ni * 8 + (lane >> 2);
                bf[ni][0] = __float_as_uint(Bs[r * GSTRIDE + kb]);
                bf[ni][1] = __float_as_uint(Bs[r * GSTRIDE + kb + 4]);
            }
            #pragma unroll
            for (int mi = 0; mi < 4; mi++)
                #pragma unroll
                for (int ni = 0; ni < 4; ni++)
                    mma_tf32(acc[mi][ni],
                             af[mi][0], af[mi][1], af[mi][2], af[mi][3],
                             bf[ni][0], bf[ni][1]);
        }
        __syncthreads();
    }

    // epilogue
    #pragma unroll
    for (int mi = 0; mi < 4; mi++) {
        #pragma unroll
        for (int ni = 0; ni < 4; ni++) {
            int row = m0 + wm + mi * 16 + (lane >> 2);
            int col = n0 + wn + ni * 8 + (lane & 3) * 2;
            float2 v0 = make_float2(acc[mi][ni][0], acc[mi][ni][1]);
            float2 v1 = make_float2(acc[mi][ni][2], acc[mi][ni][3]);
            if (EPI == 1) {
                float2 r0 = *reinterpret_cast<const float2*>(Res + (size_t)row * N + col);
                float2 r1 = *reinterpret_cast<const float2*>(Res + (size_t)(row + 8) * N + col);
                v0.x += r0.x; v0.y += r0.y;
                v1.x += r1.x; v1.y += r1.y;
            } else if (EPI == 2) {
                v0.x = gelu_exact(v0.x); v0.y = gelu_exact(v0.y);
                v1.x = gelu_exact(v1.x); v1.y = gelu_exact(v1.y);
            }
            *reinterpret_cast<float2*>(D + (size_t)row * N + col) = v0;
            *reinterpret_cast<float2*>(D + (size_t)(row + 8) * N + col) = v1;
        }
    }
}

// ---------------- launch ----------------
extern "C" void kernel_launch(void* const* d_in, const int* in_sizes, int n_in,
                              void* d_out, int out_size)
{
    (void)in_sizes; (void)n_in; (void)out_size;
    const float* x        = (const float*)d_in[0];
    const float* up       = (const float*)d_in[1];
    const float* down     = (const float*)d_in[2];
    const float* w_out    = (const float*)d_in[3];
    const float* mru_w    = (const float*)d_in[4];
    const float* ffn_w    = (const float*)d_in[5];
    const float* ffn_up   = (const float*)d_in[6];
    const float* ffn_down = (const float*)d_in[7];
    float* out = (float*)d_out;
    float* out_states = out + (size_t)NTOK * EE;

    float *p_y, *p_x1, *p_h2, *p_g;
    cudaGetSymbolAddress((void**)&p_y,  g_y);
    cudaGetSymbolAddress((void**)&p_x1, g_x1);
    cudaGetSymbolAddress((void**)&p_h2, g_h2);
    cudaGetSymbolAddress((void**)&p_g,  g_g);

    // MRU branch
    k_ln_M<<<NTOK, 256>>>(x, mru_w, up);
    k_chunkprod<<<BB * HH * NCHUNK, 64>>>();
    k_scanchunks<<<BB * HH, 64>>>();
    k_states_y<<<BB * HH * NCHUNK, 64>>>(down, out_states);

    // x1 = x + y @ w_out^T    [16384,1024] x [1024,1024]
    {
        dim3 grid(EE / 128, NTOK / 128);
        tf32gemm_nt<1><<<grid, 256>>>(p_y, w_out, x, p_x1, NTOK, EE, EE);
    }
    // h2 = LN(x1)
    k_ln<<<NTOK, 256>>>(p_x1, ffn_w, p_h2);
    // g = gelu(h2 @ ffn_up^T)   [16384,4096]
    {
        dim3 grid(DFF / 128, NTOK / 128);
        tf32gemm_nt<2><<<grid, 256>>>(p_h2, ffn_up, nullptr, p_g, NTOK, DFF, EE);
    }
    // out = x1 + g @ ffn_down^T
    {
        dim3 grid(EE / 128, NTOK / 128);
        tf32gemm_nt<1><<<grid, 256>>>(p_g, ffn_down, p_x1, out, NTOK, EE, DFF);
    }
}